// round 12
// baseline (speedup 1.0000x reference)
#include <cuda_runtime.h>
#include <cuda_bf16.h>
#include <cstdint>

// ---------------------------------------------------------------------------
// SlotGCN: 2-layer GCN. R12: GEMM occupancy fix — 104KB tiles (2 CTAs/SM),
// A-fragments hoisted to registers across passes, batched B-LDSM + MMA burst.
// Unchanged: 3-kernel CSR chain (state-cycled), side-stream overlap,
// pre-scaled h2 (gather2 = pure adds).
// N=50000, E=600000, C1=128, C2=64, fp32. Edge dtype auto-detected per block.
// ---------------------------------------------------------------------------

#define MAXN 50000
#define MAXE 600000
#define SCAN_B 512

__device__ float g_h1[MAXN * 128];
__device__ float g_a1[MAXN * 128];
__device__ float g_h2[MAXN * 64];    // main path: pre-scaled by dinv
__device__ float g_dinv[MAXN];
__device__ int   g_cnt[MAXN];        // zeroed by scanA after use
__device__ int   g_rowptr[MAXN];     // start offsets
__device__ int   g_pos[MAXN];        // build cursors; post-build = end offsets
__device__ int   g_csr[MAXE];
__device__ int   g_total;            // reset by build

// ======================= MMA + ldmatrix helpers (sm_75+) =====================
__device__ __forceinline__ void mma_bf16(float* d,
                                         uint32_t a0, uint32_t a1,
                                         uint32_t a2, uint32_t a3,
                                         uint32_t b0, uint32_t b1) {
    asm volatile(
        "mma.sync.aligned.m16n8k16.row.col.f32.bf16.bf16.f32 "
        "{%0,%1,%2,%3}, {%4,%5,%6,%7}, {%8,%9}, {%0,%1,%2,%3};"
        : "+f"(d[0]), "+f"(d[1]), "+f"(d[2]), "+f"(d[3])
        : "r"(a0), "r"(a1), "r"(a2), "r"(a3), "r"(b0), "r"(b1));
}

#define LDSM_X4(r0, r1, r2, r3, addr) \
    asm volatile("ldmatrix.sync.aligned.m8n8.x4.shared.b16 {%0,%1,%2,%3}, [%4];" \
                 : "=r"(r0), "=r"(r1), "=r"(r2), "=r"(r3) : "r"(addr))

__device__ __forceinline__ uint32_t sptr(const void* p) {
    return (uint32_t)__cvta_generic_to_shared(p);
}

__device__ __forceinline__ uint32_t pack_bf16x2(float x, float y) {
    __nv_bfloat162 h = __floats2bfloat162_rn(x, y);
    return *reinterpret_cast<uint32_t*>(&h);
}

// ======================= bf16-split GEMM (ldmatrix, 2 CTA/SM) ================
// H[N,CN] = X[N,128] @ W[128,CN] (* optional row scale), 3-pass bf16 split.
// CTA: 256 threads (8 warps), ROWS x CN tile.
//   warp w: rows (w % (ROWS/16))*16 .. +15, cols (w / (ROWS/16))*64 .. +63.
// SMEM: a_hi/a_lo [ROWS][KP], b_hi/b_lo [CN][KP] (W transposed), KP=136.
// A fragments live in registers across passes; B LDSMs batched per k-step.
template <int CN, int ROWS, bool SCALE_OUT>
__device__ __forceinline__ void gemm_ldsm_body(const float* __restrict__ X,
                                               const float* __restrict__ W,
                                               float* __restrict__ H, int N) {
    constexpr int KP = 136;
    constexpr int RG = ROWS / 16;            // row groups
    extern __shared__ __nv_bfloat16 smbf[];
    __nv_bfloat16* a_hi = smbf;
    __nv_bfloat16* a_lo = a_hi + ROWS * KP;
    __nv_bfloat16* b_hi = a_lo + ROWS * KP;
    __nv_bfloat16* b_lo = b_hi + CN * KP;

    const int tid  = threadIdx.x;
    const int lane = tid & 31;
    const int wrp  = tid >> 5;
    const long long row0 = (long long)blockIdx.x * ROWS;

    // ---- stage X tile -> a_hi/a_lo (vectorized u32 stores) ----
    for (int i = tid; i < ROWS * 32; i += 256) {
        int r = i >> 5, c = (i & 31) << 2;
        float4 v = make_float4(0.f, 0.f, 0.f, 0.f);
        if (row0 + r < N)
            v = *reinterpret_cast<const float4*>(X + (row0 + r) * 128 + c);
        __nv_bfloat16 h0 = __float2bfloat16(v.x), h1 = __float2bfloat16(v.y);
        __nv_bfloat16 h2 = __float2bfloat16(v.z), h3 = __float2bfloat16(v.w);
        float l0 = v.x - __bfloat162float(h0), l1 = v.y - __bfloat162float(h1);
        float l2 = v.z - __bfloat162float(h2), l3 = v.w - __bfloat162float(h3);
        uint32_t* ph = (uint32_t*)&a_hi[r * KP + c];
        uint32_t* pl = (uint32_t*)&a_lo[r * KP + c];
        ph[0] = (uint32_t)__bfloat16_as_ushort(h0) |
                ((uint32_t)__bfloat16_as_ushort(h1) << 16);
        ph[1] = (uint32_t)__bfloat16_as_ushort(h2) |
                ((uint32_t)__bfloat16_as_ushort(h3) << 16);
        pl[0] = pack_bf16x2(l0, l1);
        pl[1] = pack_bf16x2(l2, l3);
    }
    // ---- stage W transposed -> b_hi/b_lo: b[n][k] = W[k][n] ----
    for (int i = tid; i < 128 * (CN / 4); i += 256) {
        int kk = i / (CN / 4), nn = (i % (CN / 4)) * 4;
        float4 v = *reinterpret_cast<const float4*>(W + kk * CN + nn);
        float vv[4] = {v.x, v.y, v.z, v.w};
#pragma unroll
        for (int j = 0; j < 4; j++) {
            __nv_bfloat16 h = __float2bfloat16(vv[j]);
            b_hi[(nn + j) * KP + kk] = h;
            b_lo[(nn + j) * KP + kk] =
                __float2bfloat16(vv[j] - __bfloat162float(h));
        }
    }
    __syncthreads();

    // ---- ldmatrix offsets ----
    const int lrow = lane & 7;
    const int seg  = lane >> 3;                    // 0..3
    const int arow0 = (wrp % RG) * 16;
    const int nbase = (wrp / RG) * 64;
    const int a_off = (arow0 + (seg & 1) * 8 + lrow) * KP + (seg >> 1) * 8;
    const int b_off = (nbase + (seg >> 1) * 8 + lrow) * KP + (seg & 1) * 8;

    float acc[8][4];
#pragma unroll
    for (int t = 0; t < 8; t++) {
        acc[t][0] = 0.f; acc[t][1] = 0.f; acc[t][2] = 0.f; acc[t][3] = 0.f;
    }

    uint32_t Af[8][4];                              // A frags, all 8 k-steps
    const uint32_t ahib = sptr(a_hi) + a_off * 2;
    const uint32_t alob = sptr(a_lo) + a_off * 2;
    const uint32_t bhib = sptr(b_hi) + b_off * 2;
    const uint32_t blob = sptr(b_lo) + b_off * 2;

#pragma unroll
    for (int ks = 0; ks < 8; ks++)
        LDSM_X4(Af[ks][0], Af[ks][1], Af[ks][2], Af[ks][3], ahib + ks * 32);

#pragma unroll
    for (int pass = 0; pass < 3; pass++) {
        if (pass == 2) {                            // switch A to lo frags
#pragma unroll
            for (int ks = 0; ks < 8; ks++)
                LDSM_X4(Af[ks][0], Af[ks][1], Af[ks][2], Af[ks][3],
                        alob + ks * 32);
        }
        const uint32_t bb = (pass == 1) ? blob : bhib;
#pragma unroll
        for (int ks = 0; ks < 8; ks++) {
            uint32_t Bf[4][4];
#pragma unroll
            for (int p = 0; p < 4; p++)
                LDSM_X4(Bf[p][0], Bf[p][1], Bf[p][2], Bf[p][3],
                        bb + (p * 16 * KP + ks * 16) * 2);
#pragma unroll
            for (int p = 0; p < 4; p++) {
                mma_bf16(acc[2 * p],     Af[ks][0], Af[ks][1], Af[ks][2],
                         Af[ks][3], Bf[p][0], Bf[p][1]);
                mma_bf16(acc[2 * p + 1], Af[ks][0], Af[ks][1], Af[ks][2],
                         Af[ks][3], Bf[p][2], Bf[p][3]);
            }
        }
    }

    // ---- epilogue ----
    const int r0 = arow0 + (lane >> 2);
    const int c0 = (lane & 3) * 2;
    long long gr0 = row0 + r0;
    long long gr1 = gr0 + 8;
    float dd0 = 1.f, dd1 = 1.f;
    if (SCALE_OUT) {
        dd0 = (gr0 < N) ? g_dinv[gr0] : 0.f;
        dd1 = (gr1 < N) ? g_dinv[gr1] : 0.f;
    }
#pragma unroll
    for (int t = 0; t < 8; t++) {
        int col = nbase + t * 8 + c0;
        if (gr0 < N)
            *reinterpret_cast<float2*>(&H[gr0 * CN + col]) =
                make_float2(acc[t][0] * dd0, acc[t][1] * dd0);
        if (gr1 < N)
            *reinterpret_cast<float2*>(&H[gr1 * CN + col]) =
                make_float2(acc[t][2] * dd1, acc[t][3] * dd1);
    }
}

// gemm1: 64-row x 128-col tiles. smem = (2*64*136 + 2*128*136)*2 = 104448 B.
__global__ void __launch_bounds__(256, 2)
gemm1_mma(const float* __restrict__ X, const float* __restrict__ W, int N) {
    gemm_ldsm_body<128, 64, false>(X, W, g_h1, N);
}
// gemm2: 128-row x 64-col tiles, writes h2' = (a1 @ W2) * dinv[row].
__global__ void __launch_bounds__(256, 2)
gemm2_mma(const float* __restrict__ W, int N) {
    gemm_ldsm_body<64, 128, true>(g_a1, W, g_h2, N);
}

// ======================= gather1 (standalone, high occupancy) ===============
__global__ void gather1_kernel(const float* __restrict__ b1, int N) {
    int w = (blockIdx.x * blockDim.x + threadIdx.x) >> 5;
    int lane = threadIdx.x & 31;
    if (w >= N) return;
    float dd = g_dinv[w];
    const float4* h1v = reinterpret_cast<const float4*>(g_h1);
    float4 v = h1v[(long long)w * 32 + lane];
    float4 acc = make_float4(v.x * dd, v.y * dd, v.z * dd, v.w * dd);
    int j  = g_rowptr[w];
    int j1 = g_pos[w];
    for (; j + 3 < j1; j += 4) {
        int s0 = g_csr[j], s1 = g_csr[j + 1], s2 = g_csr[j + 2], s3 = g_csr[j + 3];
        float w0 = g_dinv[s0], w1 = g_dinv[s1], w2 = g_dinv[s2], w3 = g_dinv[s3];
        float4 u0 = h1v[(long long)s0 * 32 + lane];
        float4 u1 = h1v[(long long)s1 * 32 + lane];
        float4 u2 = h1v[(long long)s2 * 32 + lane];
        float4 u3 = h1v[(long long)s3 * 32 + lane];
        acc.x = fmaf(u0.x, w0, acc.x); acc.y = fmaf(u0.y, w0, acc.y);
        acc.z = fmaf(u0.z, w0, acc.z); acc.w = fmaf(u0.w, w0, acc.w);
        acc.x = fmaf(u1.x, w1, acc.x); acc.y = fmaf(u1.y, w1, acc.y);
        acc.z = fmaf(u1.z, w1, acc.z); acc.w = fmaf(u1.w, w1, acc.w);
        acc.x = fmaf(u2.x, w2, acc.x); acc.y = fmaf(u2.y, w2, acc.y);
        acc.z = fmaf(u2.z, w2, acc.z); acc.w = fmaf(u2.w, w2, acc.w);
        acc.x = fmaf(u3.x, w3, acc.x); acc.y = fmaf(u3.y, w3, acc.y);
        acc.z = fmaf(u3.z, w3, acc.z); acc.w = fmaf(u3.w, w3, acc.w);
    }
    for (; j < j1; ++j) {
        int s0 = g_csr[j];
        float w0 = g_dinv[s0];
        float4 u0 = h1v[(long long)s0 * 32 + lane];
        acc.x = fmaf(u0.x, w0, acc.x); acc.y = fmaf(u0.y, w0, acc.y);
        acc.z = fmaf(u0.z, w0, acc.z); acc.w = fmaf(u0.w, w0, acc.w);
    }
    float4 bb = reinterpret_cast<const float4*>(b1)[lane];
    float4 o;
    o.x = fmaxf(fmaf(acc.x, dd, bb.x), 0.f);
    o.y = fmaxf(fmaf(acc.y, dd, bb.y), 0.f);
    o.z = fmaxf(fmaf(acc.z, dd, bb.z), 0.f);
    o.w = fmaxf(fmaf(acc.w, dd, bb.w), 0.f);
    reinterpret_cast<float4*>(g_a1)[(long long)w * 32 + lane] = o;
}

// ======================= gather2: pure adds over pre-scaled h2' =============
__global__ void gather2_kernel(const float* __restrict__ b2,
                               float* __restrict__ out, int N) {
    int w = (blockIdx.x * blockDim.x + threadIdx.x) >> 5;
    int lane = threadIdx.x & 31;
    if (w >= N) return;
    float dd = g_dinv[w];
    const float2* h2v = reinterpret_cast<const float2*>(g_h2);
    float2 acc = h2v[(long long)w * 32 + lane];   // self: h2'[w]
    int j  = g_rowptr[w];
    int j1 = g_pos[w];
    for (; j + 3 < j1; j += 4) {
        int s0 = g_csr[j], s1 = g_csr[j + 1], s2 = g_csr[j + 2], s3 = g_csr[j + 3];
        float2 u0 = h2v[(long long)s0 * 32 + lane];
        float2 u1 = h2v[(long long)s1 * 32 + lane];
        float2 u2 = h2v[(long long)s2 * 32 + lane];
        float2 u3 = h2v[(long long)s3 * 32 + lane];
        acc.x += u0.x + u1.x + u2.x + u3.x;
        acc.y += u0.y + u1.y + u2.y + u3.y;
    }
    for (; j < j1; ++j) {
        int s0 = g_csr[j];
        float2 u0 = h2v[(long long)s0 * 32 + lane];
        acc.x += u0.x; acc.y += u0.y;
    }
    float2 bb = reinterpret_cast<const float2*>(b2)[lane];
    float2 o;
    o.x = fmaf(acc.x, dd, bb.x);
    o.y = fmaf(acc.y, dd, bb.y);
    reinterpret_cast<float2*>(out)[(long long)w * 32 + lane] = o;
}

// ======================= CSR build chain (3 kernels) =========================
__device__ __forceinline__ int block_detect_is64(const int* ei32, long long e,
                                                 int E, int* s_nz) {
    if (threadIdx.x == 0) *s_nz = 0;
    __syncthreads();
    long long es = (e < E) ? e : (long long)(E - 1);
    if (ei32[2 * es + 1] != 0) *s_nz = 1;   // benign race
    __syncthreads();
    return (*s_nz == 0);
}

__global__ void deg_kernel(const void* __restrict__ ei, int E, int N) {
    __shared__ int s_nz;
    long long e0 = (long long)(blockIdx.x * blockDim.x + threadIdx.x) * 2;
    int is64 = block_detect_is64((const int*)ei, e0, E, &s_nz);
    if (e0 >= E) return;
    bool two = (e0 + 1 < E);
    int d0, d1 = -1;
    if (is64) {
        const long long* p = (const long long*)ei + E + e0;
        if (two) { longlong2 q = *(const longlong2*)p; d0 = (int)q.x; d1 = (int)q.y; }
        else d0 = (int)p[0];
    } else {
        const int* p = (const int*)ei + E + e0;
        if (two) { int2 q = *(const int2*)p; d0 = q.x; d1 = q.y; }
        else d0 = p[0];
    }
    if ((unsigned)d0 < (unsigned)N) atomicAdd(&g_cnt[d0], 1);
    if (two && (unsigned)d1 < (unsigned)N) atomicAdd(&g_cnt[d1], 1);
}

__global__ void scanA_kernel(int N) {
    __shared__ int sh[SCAN_B];
    __shared__ int s_base;
    int t = threadIdx.x;
    int i = blockIdx.x * SCAN_B + t;
    int v = (i < N) ? g_cnt[i] : 0;
    if (i < N) {
        g_dinv[i] = rsqrtf((float)v + 1.0f);
        g_cnt[i] = 0;                      // state-cycle for next call
    }
    sh[t] = v;
    __syncthreads();
#pragma unroll
    for (int o = 1; o < SCAN_B; o <<= 1) {
        int x = (t >= o) ? sh[t - o] : 0;
        __syncthreads();
        sh[t] += x;
        __syncthreads();
    }
    if (t == SCAN_B - 1) s_base = atomicAdd(&g_total, sh[SCAN_B - 1]);
    __syncthreads();
    if (i < N) {
        int r = s_base + sh[t] - v;
        g_rowptr[i] = r;
        g_pos[i] = r;
    }
}

__global__ void build_kernel(const void* __restrict__ ei, int E, int N) {
    __shared__ int s_nz;
    long long e0 = (long long)(blockIdx.x * blockDim.x + threadIdx.x) * 2;
    int is64 = block_detect_is64((const int*)ei, e0, E, &s_nz);
    if (e0 == 0) g_total = 0;              // state-cycle for next call
    if (e0 >= E) return;
    bool two = (e0 + 1 < E);
    int s0, s1 = -1, d0, d1 = -1;
    if (is64) {
        const long long* ps = (const long long*)ei + e0;
        const long long* pd = (const long long*)ei + E + e0;
        if (two) {
            longlong2 qs = *(const longlong2*)ps, qd = *(const longlong2*)pd;
            s0 = (int)qs.x; s1 = (int)qs.y; d0 = (int)qd.x; d1 = (int)qd.y;
        } else { s0 = (int)ps[0]; d0 = (int)pd[0]; }
    } else {
        const int* ps = (const int*)ei + e0;
        const int* pd = (const int*)ei + E + e0;
        if (two) {
            int2 qs = *(const int2*)ps, qd = *(const int2*)pd;
            s0 = qs.x; s1 = qs.y; d0 = qd.x; d1 = qd.y;
        } else { s0 = ps[0]; d0 = pd[0]; }
    }
    if ((unsigned)d0 < (unsigned)N && (unsigned)s0 < (unsigned)N) {
        int p = atomicAdd(&g_pos[d0], 1);
        if (p < MAXE) g_csr[p] = s0;
    }
    if (two && (unsigned)d1 < (unsigned)N && (unsigned)s1 < (unsigned)N) {
        int p = atomicAdd(&g_pos[d1], 1);
        if (p < MAXE) g_csr[p] = s1;
    }
}

// ======================= fallback path (shape guard) =========================
template <int C>
__device__ __forceinline__ void gemm_body(const float* __restrict__ X,
                                          const float* __restrict__ W,
                                          float* __restrict__ H, int N) {
    constexpr int CT = C / 4;
    __shared__ float xs[32][33];
    __shared__ float ws[32][C];
    const int tid = threadIdx.x;
    const int ct = tid % CT;
    const int rt = tid / CT;
    const int row0 = blockIdx.x * 32;
    const int nthr = CT * 8;
    float acc[4][4];
#pragma unroll
    for (int r = 0; r < 4; r++)
#pragma unroll
        for (int c = 0; c < 4; c++) acc[r][c] = 0.f;
    for (int k0 = 0; k0 < 128; k0 += 32) {
        for (int i = tid; i < 32 * 32; i += nthr) {
            int r = i >> 5, k = i & 31;
            int grow = row0 + r;
            xs[r][k] = (grow < N) ? X[(long long)grow * 128 + k0 + k] : 0.f;
        }
        for (int i = tid; i < 32 * C; i += nthr) {
            int k = i / C, c = i % C;
            ws[k][c] = W[(k0 + k) * C + c];
        }
        __syncthreads();
#pragma unroll
        for (int k = 0; k < 32; k++) {
            float4 b = *reinterpret_cast<const float4*>(&ws[k][ct * 4]);
#pragma unroll
            for (int r = 0; r < 4; r++) {
                float a = xs[rt * 4 + r][k];
                acc[r][0] = fmaf(a, b.x, acc[r][0]);
                acc[r][1] = fmaf(a, b.y, acc[r][1]);
                acc[r][2] = fmaf(a, b.z, acc[r][2]);
                acc[r][3] = fmaf(a, b.w, acc[r][3]);
            }
        }
        __syncthreads();
    }
#pragma unroll
    for (int r = 0; r < 4; r++) {
        int grow = row0 + rt * 4 + r;
        if (grow < N) {
            float4 v = make_float4(acc[r][0], acc[r][1], acc[r][2], acc[r][3]);
            *reinterpret_cast<float4*>(&H[(long long)grow * C + ct * 4]) = v;
        }
    }
}
__global__ void gemm1_simt(const float* __restrict__ X,
                           const float* __restrict__ W, int N) {
    gemm_body<128>(X, W, g_h1, N);
}
__global__ void gemm2_simt(const float* __restrict__ W, int N) {
    gemm_body<64>(g_a1, W, g_h2, N);
}

__global__ void gather2_fb(const float* __restrict__ b2,
                           float* __restrict__ out, int N) {
    int w = (blockIdx.x * blockDim.x + threadIdx.x) >> 5;
    int lane = threadIdx.x & 31;
    if (w >= N) return;
    float dd = g_dinv[w];
    const float2* h2v = reinterpret_cast<const float2*>(g_h2);
    float2 v = h2v[(long long)w * 32 + lane];
    float2 acc = make_float2(v.x * dd, v.y * dd);
    int j = g_rowptr[w];
    int j1 = g_pos[w];
    for (; j < j1; ++j) {
        int s0 = g_csr[j];
        float w0 = g_dinv[s0];
        float2 u0 = h2v[(long long)s0 * 32 + lane];
        acc.x = fmaf(u0.x, w0, acc.x); acc.y = fmaf(u0.y, w0, acc.y);
    }
    float2 bb = reinterpret_cast<const float2*>(b2)[lane];
    float2 o;
    o.x = fmaf(acc.x, dd, bb.x);
    o.y = fmaf(acc.y, dd, bb.y);
    reinterpret_cast<float2*>(out)[(long long)w * 32 + lane] = o;
}

// ======================= host-side stream/event (once) ======================
struct GcnStreams {
    cudaStream_t s1 = nullptr;
    cudaEvent_t e0 = nullptr, e1 = nullptr;
    bool ok = false;
    GcnStreams() {
        if (cudaStreamCreateWithFlags(&s1, cudaStreamNonBlocking) != cudaSuccess) return;
        if (cudaEventCreateWithFlags(&e0, cudaEventDisableTiming) != cudaSuccess) return;
        if (cudaEventCreateWithFlags(&e1, cudaEventDisableTiming) != cudaSuccess) return;
        ok = true;
    }
};
static GcnStreams g_str;

// ======================= launch ==============================================
extern "C" void kernel_launch(void* const* d_in, const int* in_sizes, int n_in,
                              void* d_out, int out_size) {
    const float* x   = (const float*)d_in[0];
    const void*  ei  = d_in[1];
    const float* W1  = (const float*)d_in[2];
    const float* b1  = (const float*)d_in[3];
    const float* W2  = (const float*)d_in[4];
    const float* b2  = (const float*)d_in[5];
    float*       out = (float*)d_out;

    const int N = in_sizes[0] / 128;
    const int E = in_sizes[1] / 2;
    const bool tc_ok = (in_sizes[2] == 128 * 128) && (in_sizes[4] == 128 * 64);

    const int TB = 256;
    const int nb = (N + SCAN_B - 1) / SCAN_B;
    const int ebl2 = (E / 2 + TB) / TB;

    // gemm1: a(64 rows) + b(128 cols); gemm2: a(128 rows) + b(64 cols)
    const int smem1 = (2 * 64 * 136 + 2 * 128 * 136) * 2;   // 104448
    const int smem2 = (2 * 128 * 136 + 2 * 64 * 136) * 2;   // 104448
    cudaFuncSetAttribute(gemm1_mma,
                         cudaFuncAttributeMaxDynamicSharedMemorySize, smem1);
    cudaFuncSetAttribute(gemm2_mma,
                         cudaFuncAttributeMaxDynamicSharedMemorySize, smem2);

    const bool fork = g_str.ok;
    cudaStream_t sc = fork ? g_str.s1 : (cudaStream_t)0;

    if (fork) {
        cudaEventRecord(g_str.e0, 0);
        cudaStreamWaitEvent(sc, g_str.e0, 0);
    }

    // CSR build chain (side stream): deg -> scanA -> build
    deg_kernel<<<ebl2, TB, 0, sc>>>(ei, E, N);
    scanA_kernel<<<nb, SCAN_B, 0, sc>>>(N);
    build_kernel<<<ebl2, TB, 0, sc>>>(ei, E, N);

    // GEMM1 concurrently on main stream
    if (tc_ok) {
        gemm1_mma<<<(N + 63) / 64, 256, smem1>>>(x, W1, N);
    } else {
        gemm1_simt<<<(N + 31) / 32, 256>>>(x, W1, N);
    }

    if (fork) {
        cudaEventRecord(g_str.e1, sc);
        cudaStreamWaitEvent((cudaStream_t)0, g_str.e1, 0);
    }

    gather1_kernel<<<(N * 32 + TB - 1) / TB, TB>>>(b1, N);

    if (tc_ok) {
        gemm2_mma<<<(N + 127) / 128, 256, smem2>>>(W2, N);
        gather2_kernel<<<(N * 32 + TB - 1) / TB, TB>>>(b2, out, N);
    } else {
        gemm2_simt<<<(N + 31) / 32, 128>>>(W2, N);
        gather2_fb<<<(N * 32 + TB - 1) / TB, TB>>>(b2, out, N);
    }
}

// round 13
// speedup vs baseline: 1.3297x; 1.3297x over previous
#include <cuda_runtime.h>
#include <cuda_bf16.h>
#include <cstdint>

// ---------------------------------------------------------------------------
// SlotGCN: 2-layer GCN. R13: convert-once prep kernel (X,W -> bf16 hi/lo
// globals), GEMM staging = pure uint4 copies (no per-CTA converts),
// gather1 emits a1 as bf16 hi/lo. ldmatrix GEMMs, 2 CTA/SM.
// N=50000, E=600000, C1=128, C2=64, fp32. Edge dtype auto-detected per block.
// ---------------------------------------------------------------------------

#define MAXN 50000
#define MAXE 600000
#define SCAN_B 512

__device__ float g_h1[MAXN * 128];
__device__ float g_a1[MAXN * 128];             // fallback path only
__device__ float g_h2[MAXN * 64];              // pre-scaled by dinv
__device__ float g_dinv[MAXN];
__device__ int   g_cnt[MAXN];
__device__ int   g_rowptr[MAXN];
__device__ int   g_pos[MAXN];
__device__ int   g_csr[MAXE];
__device__ int   g_total;

// bf16 hi/lo split storage (converted once per call)
__device__ __nv_bfloat16 g_xhi[MAXN * 128];
__device__ __nv_bfloat16 g_xlo[MAXN * 128];
__device__ __nv_bfloat16 g_a1hi[MAXN * 128];
__device__ __nv_bfloat16 g_a1lo[MAXN * 128];
__device__ __nv_bfloat16 g_w1hi[128 * 128];    // transposed: [n][k]
__device__ __nv_bfloat16 g_w1lo[128 * 128];
__device__ __nv_bfloat16 g_w2hi[64 * 128];     // transposed: [n][k]
__device__ __nv_bfloat16 g_w2lo[64 * 128];

// ======================= helpers =============================================
__device__ __forceinline__ void mma_bf16(float* d,
                                         uint32_t a0, uint32_t a1,
                                         uint32_t a2, uint32_t a3,
                                         uint32_t b0, uint32_t b1) {
    asm volatile(
        "mma.sync.aligned.m16n8k16.row.col.f32.bf16.bf16.f32 "
        "{%0,%1,%2,%3}, {%4,%5,%6,%7}, {%8,%9}, {%0,%1,%2,%3};"
        : "+f"(d[0]), "+f"(d[1]), "+f"(d[2]), "+f"(d[3])
        : "r"(a0), "r"(a1), "r"(a2), "r"(a3), "r"(b0), "r"(b1));
}

#define LDSM_X4(r0, r1, r2, r3, addr) \
    asm volatile("ldmatrix.sync.aligned.m8n8.x4.shared.b16 {%0,%1,%2,%3}, [%4];" \
                 : "=r"(r0), "=r"(r1), "=r"(r2), "=r"(r3) : "r"(addr))

__device__ __forceinline__ uint32_t sptr(const void* p) {
    return (uint32_t)__cvta_generic_to_shared(p);
}
__device__ __forceinline__ uint32_t pack_bf16x2(float x, float y) {
    __nv_bfloat162 h = __floats2bfloat162_rn(x, y);
    return *reinterpret_cast<uint32_t*>(&h);
}
__device__ __forceinline__ void split2(float x, float y,
                                       uint32_t& hi, uint32_t& lo) {
    __nv_bfloat16 hx = __float2bfloat16(x), hy = __float2bfloat16(y);
    hi = (uint32_t)__bfloat16_as_ushort(hx) |
         ((uint32_t)__bfloat16_as_ushort(hy) << 16);
    lo = pack_bf16x2(x - __bfloat162float(hx), y - __bfloat162float(hy));
}

// ======================= prep: convert X, W1, W2 once ========================
__global__ void prep_kernel(const float* __restrict__ X,
                            const float* __restrict__ W1,
                            const float* __restrict__ W2, int N) {
    int idx = blockIdx.x * blockDim.x + threadIdx.x;
    // X: N*32 float4 chunks
    if (idx < N * 32) {
        float4 v = reinterpret_cast<const float4*>(X)[idx];
        uint32_t h0, l0, h1, l1;
        split2(v.x, v.y, h0, l0);
        split2(v.z, v.w, h1, l1);
        uint32_t* xh = reinterpret_cast<uint32_t*>(g_xhi);
        uint32_t* xl = reinterpret_cast<uint32_t*>(g_xlo);
        xh[idx * 2] = h0; xh[idx * 2 + 1] = h1;
        xl[idx * 2] = l0; xl[idx * 2 + 1] = l1;
    }
    // W1 transpose: 128x128
    if (idx < 128 * 128) {
        int k = idx >> 7, n = idx & 127;
        float v = W1[k * 128 + n];
        __nv_bfloat16 h = __float2bfloat16(v);
        g_w1hi[n * 128 + k] = h;
        g_w1lo[n * 128 + k] = __float2bfloat16(v - __bfloat162float(h));
    }
    // W2 transpose: 128x64
    if (idx < 128 * 64) {
        int k = idx >> 6, n = idx & 63;
        float v = W2[k * 64 + n];
        __nv_bfloat16 h = __float2bfloat16(v);
        g_w2hi[n * 128 + k] = h;
        g_w2lo[n * 128 + k] = __float2bfloat16(v - __bfloat162float(h));
    }
}

// ======================= bf16-split GEMM (copy staging) ======================
// H[N,CN] = A[N,128] @ B^T (B transposed [CN][128]), 3-pass hi/lo split.
// CTA: 256 threads (8 warps), ROWS x CN tile, 2 CTA/SM (104448 B smem).
template <int CN, int ROWS, bool SCALE_OUT>
__device__ __forceinline__ void gemm_ldsm_body(
    const __nv_bfloat16* __restrict__ Ahi, const __nv_bfloat16* __restrict__ Alo,
    const __nv_bfloat16* __restrict__ Bhi, const __nv_bfloat16* __restrict__ Blo,
    float* __restrict__ H, int N) {
    constexpr int KP = 136;
    constexpr int RG = ROWS / 16;
    extern __shared__ __nv_bfloat16 smbf[];
    __nv_bfloat16* a_hi = smbf;
    __nv_bfloat16* a_lo = a_hi + ROWS * KP;
    __nv_bfloat16* b_hi = a_lo + ROWS * KP;
    __nv_bfloat16* b_lo = b_hi + CN * KP;

    const int tid  = threadIdx.x;
    const int lane = tid & 31;
    const int wrp  = tid >> 5;
    const long long row0 = (long long)blockIdx.x * ROWS;

    // ---- stage A tile: pure uint4 copies (8 bf16 each) ----
    for (int i = tid; i < ROWS * 16; i += 256) {
        int r = i >> 4, seg = (i & 15) * 8;
        uint4 vh = make_uint4(0, 0, 0, 0), vl = make_uint4(0, 0, 0, 0);
        if (row0 + r < N) {
            vh = *reinterpret_cast<const uint4*>(Ahi + (row0 + r) * 128 + seg);
            vl = *reinterpret_cast<const uint4*>(Alo + (row0 + r) * 128 + seg);
        }
        *reinterpret_cast<uint4*>(&a_hi[r * KP + seg]) = vh;
        *reinterpret_cast<uint4*>(&a_lo[r * KP + seg]) = vl;
    }
    // ---- stage B tile (already transposed in global) ----
    for (int i = tid; i < CN * 16; i += 256) {
        int n = i >> 4, seg = (i & 15) * 8;
        *reinterpret_cast<uint4*>(&b_hi[n * KP + seg]) =
            *reinterpret_cast<const uint4*>(Bhi + n * 128 + seg);
        *reinterpret_cast<uint4*>(&b_lo[n * KP + seg]) =
            *reinterpret_cast<const uint4*>(Blo + n * 128 + seg);
    }
    __syncthreads();

    // ---- ldmatrix offsets ----
    const int lrow = lane & 7;
    const int seg  = lane >> 3;
    const int arow0 = (wrp % RG) * 16;
    const int nbase = (wrp / RG) * 64;
    const int a_off = (arow0 + (seg & 1) * 8 + lrow) * KP + (seg >> 1) * 8;
    const int b_off = (nbase + (seg >> 1) * 8 + lrow) * KP + (seg & 1) * 8;

    float acc[8][4];
#pragma unroll
    for (int t = 0; t < 8; t++) {
        acc[t][0] = 0.f; acc[t][1] = 0.f; acc[t][2] = 0.f; acc[t][3] = 0.f;
    }

    uint32_t Af[8][4];
    const uint32_t ahib = sptr(a_hi) + a_off * 2;
    const uint32_t alob = sptr(a_lo) + a_off * 2;
    const uint32_t bhib = sptr(b_hi) + b_off * 2;
    const uint32_t blob = sptr(b_lo) + b_off * 2;

#pragma unroll
    for (int ks = 0; ks < 8; ks++)
        LDSM_X4(Af[ks][0], Af[ks][1], Af[ks][2], Af[ks][3], ahib + ks * 32);

#pragma unroll
    for (int pass = 0; pass < 3; pass++) {
        if (pass == 2) {
#pragma unroll
            for (int ks = 0; ks < 8; ks++)
                LDSM_X4(Af[ks][0], Af[ks][1], Af[ks][2], Af[ks][3],
                        alob + ks * 32);
        }
        const uint32_t bb = (pass == 1) ? blob : bhib;
#pragma unroll
        for (int ks = 0; ks < 8; ks++) {
            uint32_t Bf[4][4];
#pragma unroll
            for (int p = 0; p < 4; p++)
                LDSM_X4(Bf[p][0], Bf[p][1], Bf[p][2], Bf[p][3],
                        bb + (p * 16 * KP + ks * 16) * 2);
#pragma unroll
            for (int p = 0; p < 4; p++) {
                mma_bf16(acc[2 * p],     Af[ks][0], Af[ks][1], Af[ks][2],
                         Af[ks][3], Bf[p][0], Bf[p][1]);
                mma_bf16(acc[2 * p + 1], Af[ks][0], Af[ks][1], Af[ks][2],
                         Af[ks][3], Bf[p][2], Bf[p][3]);
            }
        }
    }

    // ---- epilogue ----
    const int r0 = arow0 + (lane >> 2);
    const int c0 = (lane & 3) * 2;
    long long gr0 = row0 + r0;
    long long gr1 = gr0 + 8;
    float dd0 = 1.f, dd1 = 1.f;
    if (SCALE_OUT) {
        dd0 = (gr0 < N) ? g_dinv[gr0] : 0.f;
        dd1 = (gr1 < N) ? g_dinv[gr1] : 0.f;
    }
#pragma unroll
    for (int t = 0; t < 8; t++) {
        int col = nbase + t * 8 + c0;
        if (gr0 < N)
            *reinterpret_cast<float2*>(&H[gr0 * CN + col]) =
                make_float2(acc[t][0] * dd0, acc[t][1] * dd0);
        if (gr1 < N)
            *reinterpret_cast<float2*>(&H[gr1 * CN + col]) =
                make_float2(acc[t][2] * dd1, acc[t][3] * dd1);
    }
}

__global__ void __launch_bounds__(256, 2)
gemm1_mma(int N) {
    gemm_ldsm_body<128, 64, false>(g_xhi, g_xlo, g_w1hi, g_w1lo, g_h1, N);
}
__global__ void __launch_bounds__(256, 2)
gemm2_mma(int N) {
    gemm_ldsm_body<64, 128, true>(g_a1hi, g_a1lo, g_w2hi, g_w2lo, g_h2, N);
}

// ======================= gather1: emits a1 as bf16 hi/lo =====================
__global__ void gather1_kernel(const float* __restrict__ b1, int N) {
    int w = (blockIdx.x * blockDim.x + threadIdx.x) >> 5;
    int lane = threadIdx.x & 31;
    if (w >= N) return;
    float dd = g_dinv[w];
    const float4* h1v = reinterpret_cast<const float4*>(g_h1);
    float4 v = h1v[(long long)w * 32 + lane];
    float4 acc = make_float4(v.x * dd, v.y * dd, v.z * dd, v.w * dd);
    int j  = g_rowptr[w];
    int j1 = g_pos[w];
    for (; j + 3 < j1; j += 4) {
        int s0 = g_csr[j], s1 = g_csr[j + 1], s2 = g_csr[j + 2], s3 = g_csr[j + 3];
        float w0 = g_dinv[s0], w1 = g_dinv[s1], w2 = g_dinv[s2], w3 = g_dinv[s3];
        float4 u0 = h1v[(long long)s0 * 32 + lane];
        float4 u1 = h1v[(long long)s1 * 32 + lane];
        float4 u2 = h1v[(long long)s2 * 32 + lane];
        float4 u3 = h1v[(long long)s3 * 32 + lane];
        acc.x = fmaf(u0.x, w0, acc.x); acc.y = fmaf(u0.y, w0, acc.y);
        acc.z = fmaf(u0.z, w0, acc.z); acc.w = fmaf(u0.w, w0, acc.w);
        acc.x = fmaf(u1.x, w1, acc.x); acc.y = fmaf(u1.y, w1, acc.y);
        acc.z = fmaf(u1.z, w1, acc.z); acc.w = fmaf(u1.w, w1, acc.w);
        acc.x = fmaf(u2.x, w2, acc.x); acc.y = fmaf(u2.y, w2, acc.y);
        acc.z = fmaf(u2.z, w2, acc.z); acc.w = fmaf(u2.w, w2, acc.w);
        acc.x = fmaf(u3.x, w3, acc.x); acc.y = fmaf(u3.y, w3, acc.y);
        acc.z = fmaf(u3.z, w3, acc.z); acc.w = fmaf(u3.w, w3, acc.w);
    }
    for (; j < j1; ++j) {
        int s0 = g_csr[j];
        float w0 = g_dinv[s0];
        float4 u0 = h1v[(long long)s0 * 32 + lane];
        acc.x = fmaf(u0.x, w0, acc.x); acc.y = fmaf(u0.y, w0, acc.y);
        acc.z = fmaf(u0.z, w0, acc.z); acc.w = fmaf(u0.w, w0, acc.w);
    }
    float4 bb = reinterpret_cast<const float4*>(b1)[lane];
    float o0 = fmaxf(fmaf(acc.x, dd, bb.x), 0.f);
    float o1 = fmaxf(fmaf(acc.y, dd, bb.y), 0.f);
    float o2 = fmaxf(fmaf(acc.z, dd, bb.z), 0.f);
    float o3 = fmaxf(fmaf(acc.w, dd, bb.w), 0.f);
    uint32_t h0, l0, h1, l1;
    split2(o0, o1, h0, l0);
    split2(o2, o3, h1, l1);
    uint32_t* ah = reinterpret_cast<uint32_t*>(g_a1hi);
    uint32_t* al = reinterpret_cast<uint32_t*>(g_a1lo);
    long long base = (long long)w * 64 + lane * 2;
    ah[base] = h0; ah[base + 1] = h1;
    al[base] = l0; al[base + 1] = l1;
}

// ======================= gather2: pure adds over pre-scaled h2' =============
__global__ void gather2_kernel(const float* __restrict__ b2,
                               float* __restrict__ out, int N) {
    int w = (blockIdx.x * blockDim.x + threadIdx.x) >> 5;
    int lane = threadIdx.x & 31;
    if (w >= N) return;
    float dd = g_dinv[w];
    const float2* h2v = reinterpret_cast<const float2*>(g_h2);
    float2 acc = h2v[(long long)w * 32 + lane];
    int j  = g_rowptr[w];
    int j1 = g_pos[w];
    for (; j + 3 < j1; j += 4) {
        int s0 = g_csr[j], s1 = g_csr[j + 1], s2 = g_csr[j + 2], s3 = g_csr[j + 3];
        float2 u0 = h2v[(long long)s0 * 32 + lane];
        float2 u1 = h2v[(long long)s1 * 32 + lane];
        float2 u2 = h2v[(long long)s2 * 32 + lane];
        float2 u3 = h2v[(long long)s3 * 32 + lane];
        acc.x += u0.x + u1.x + u2.x + u3.x;
        acc.y += u0.y + u1.y + u2.y + u3.y;
    }
    for (; j < j1; ++j) {
        int s0 = g_csr[j];
        float2 u0 = h2v[(long long)s0 * 32 + lane];
        acc.x += u0.x; acc.y += u0.y;
    }
    float2 bb = reinterpret_cast<const float2*>(b2)[lane];
    float2 o;
    o.x = fmaf(acc.x, dd, bb.x);
    o.y = fmaf(acc.y, dd, bb.y);
    reinterpret_cast<float2*>(out)[(long long)w * 32 + lane] = o;
}

// ======================= CSR build chain (3 kernels) =========================
__device__ __forceinline__ int block_detect_is64(const int* ei32, long long e,
                                                 int E, int* s_nz) {
    if (threadIdx.x == 0) *s_nz = 0;
    __syncthreads();
    long long es = (e < E) ? e : (long long)(E - 1);
    if (ei32[2 * es + 1] != 0) *s_nz = 1;
    __syncthreads();
    return (*s_nz == 0);
}

__global__ void deg_kernel(const void* __restrict__ ei, int E, int N) {
    __shared__ int s_nz;
    long long e0 = (long long)(blockIdx.x * blockDim.x + threadIdx.x) * 2;
    int is64 = block_detect_is64((const int*)ei, e0, E, &s_nz);
    if (e0 >= E) return;
    bool two = (e0 + 1 < E);
    int d0, d1 = -1;
    if (is64) {
        const long long* p = (const long long*)ei + E + e0;
        if (two) { longlong2 q = *(const longlong2*)p; d0 = (int)q.x; d1 = (int)q.y; }
        else d0 = (int)p[0];
    } else {
        const int* p = (const int*)ei + E + e0;
        if (two) { int2 q = *(const int2*)p; d0 = q.x; d1 = q.y; }
        else d0 = p[0];
    }
    if ((unsigned)d0 < (unsigned)N) atomicAdd(&g_cnt[d0], 1);
    if (two && (unsigned)d1 < (unsigned)N) atomicAdd(&g_cnt[d1], 1);
}

__global__ void scanA_kernel(int N) {
    __shared__ int sh[SCAN_B];
    __shared__ int s_base;
    int t = threadIdx.x;
    int i = blockIdx.x * SCAN_B + t;
    int v = (i < N) ? g_cnt[i] : 0;
    if (i < N) {
        g_dinv[i] = rsqrtf((float)v + 1.0f);
        g_cnt[i] = 0;
    }
    sh[t] = v;
    __syncthreads();
#pragma unroll
    for (int o = 1; o < SCAN_B; o <<= 1) {
        int x = (t >= o) ? sh[t - o] : 0;
        __syncthreads();
        sh[t] += x;
        __syncthreads();
    }
    if (t == SCAN_B - 1) s_base = atomicAdd(&g_total, sh[SCAN_B - 1]);
    __syncthreads();
    if (i < N) {
        int r = s_base + sh[t] - v;
        g_rowptr[i] = r;
        g_pos[i] = r;
    }
}

__global__ void build_kernel(const void* __restrict__ ei, int E, int N) {
    __shared__ int s_nz;
    long long e0 = (long long)(blockIdx.x * blockDim.x + threadIdx.x) * 2;
    int is64 = block_detect_is64((const int*)ei, e0, E, &s_nz);
    if (e0 == 0) g_total = 0;
    if (e0 >= E) return;
    bool two = (e0 + 1 < E);
    int s0, s1 = -1, d0, d1 = -1;
    if (is64) {
        const long long* ps = (const long long*)ei + e0;
        const long long* pd = (const long long*)ei + E + e0;
        if (two) {
            longlong2 qs = *(const longlong2*)ps, qd = *(const longlong2*)pd;
            s0 = (int)qs.x; s1 = (int)qs.y; d0 = (int)qd.x; d1 = (int)qd.y;
        } else { s0 = (int)ps[0]; d0 = (int)pd[0]; }
    } else {
        const int* ps = (const int*)ei + e0;
        const int* pd = (const int*)ei + E + e0;
        if (two) {
            int2 qs = *(const int2*)ps, qd = *(const int2*)pd;
            s0 = qs.x; s1 = qs.y; d0 = qd.x; d1 = qd.y;
        } else { s0 = ps[0]; d0 = pd[0]; }
    }
    if ((unsigned)d0 < (unsigned)N && (unsigned)s0 < (unsigned)N) {
        int p = atomicAdd(&g_pos[d0], 1);
        if (p < MAXE) g_csr[p] = s0;
    }
    if (two && (unsigned)d1 < (unsigned)N && (unsigned)s1 < (unsigned)N) {
        int p = atomicAdd(&g_pos[d1], 1);
        if (p < MAXE) g_csr[p] = s1;
    }
}

// ======================= fallback path (shape guard) =========================
template <int C>
__device__ __forceinline__ void gemm_body(const float* __restrict__ X,
                                          const float* __restrict__ W,
                                          float* __restrict__ H, int N) {
    constexpr int CT = C / 4;
    __shared__ float xs[32][33];
    __shared__ float ws[32][C];
    const int tid = threadIdx.x;
    const int ct = tid % CT;
    const int rt = tid / CT;
    const int row0 = blockIdx.x * 32;
    const int nthr = CT * 8;
    float acc[4][4];
#pragma unroll
    for (int r = 0; r < 4; r++)
#pragma unroll
        for (int c = 0; c < 4; c++) acc[r][c] = 0.f;
    for (int k0 = 0; k0 < 128; k0 += 32) {
        for (int i = tid; i < 32 * 32; i += nthr) {
            int r = i >> 5, k = i & 31;
            int grow = row0 + r;
            xs[r][k] = (grow < N) ? X[(long long)grow * 128 + k0 + k] : 0.f;
        }
        for (int i = tid; i < 32 * C; i += nthr) {
            int k = i / C, c = i % C;
            ws[k][c] = W[(k0 + k) * C + c];
        }
        __syncthreads();
#pragma unroll
        for (int k = 0; k < 32; k++) {
            float4 b = *reinterpret_cast<const float4*>(&ws[k][ct * 4]);
#pragma unroll
            for (int r = 0; r < 4; r++) {
                float a = xs[rt * 4 + r][k];
                acc[r][0] = fmaf(a, b.x, acc[r][0]);
                acc[r][1] = fmaf(a, b.y, acc[r][1]);
                acc[r][2] = fmaf(a, b.z, acc[r][2]);
                acc[r][3] = fmaf(a, b.w, acc[r][3]);
            }
        }
        __syncthreads();
    }
#pragma unroll
    for (int r = 0; r < 4; r++) {
        int grow = row0 + rt * 4 + r;
        if (grow < N) {
            float4 v = make_float4(acc[r][0], acc[r][1], acc[r][2], acc[r][3]);
            *reinterpret_cast<float4*>(&H[(long long)grow * C + ct * 4]) = v;
        }
    }
}
__global__ void gemm1_simt(const float* __restrict__ X,
                           const float* __restrict__ W, int N) {
    gemm_body<128>(X, W, g_h1, N);
}
__global__ void gemm2_simt(const float* __restrict__ W, int N) {
    gemm_body<64>(g_a1, W, g_h2, N);
}

__global__ void gather1_fb(const float* __restrict__ b1, int N) {
    int w = (blockIdx.x * blockDim.x + threadIdx.x) >> 5;
    int lane = threadIdx.x & 31;
    if (w >= N) return;
    float dd = g_dinv[w];
    const float4* h1v = reinterpret_cast<const float4*>(g_h1);
    float4 v = h1v[(long long)w * 32 + lane];
    float4 acc = make_float4(v.x * dd, v.y * dd, v.z * dd, v.w * dd);
    int j = g_rowptr[w];
    int j1 = g_pos[w];
    for (; j < j1; ++j) {
        int s0 = g_csr[j];
        float w0 = g_dinv[s0];
        float4 u0 = h1v[(long long)s0 * 32 + lane];
        acc.x = fmaf(u0.x, w0, acc.x); acc.y = fmaf(u0.y, w0, acc.y);
        acc.z = fmaf(u0.z, w0, acc.z); acc.w = fmaf(u0.w, w0, acc.w);
    }
    float4 bb = reinterpret_cast<const float4*>(b1)[lane];
    float4 o;
    o.x = fmaxf(fmaf(acc.x, dd, bb.x), 0.f);
    o.y = fmaxf(fmaf(acc.y, dd, bb.y), 0.f);
    o.z = fmaxf(fmaf(acc.z, dd, bb.z), 0.f);
    o.w = fmaxf(fmaf(acc.w, dd, bb.w), 0.f);
    reinterpret_cast<float4*>(g_a1)[(long long)w * 32 + lane] = o;
}

__global__ void gather2_fb(const float* __restrict__ b2,
                           float* __restrict__ out, int N) {
    int w = (blockIdx.x * blockDim.x + threadIdx.x) >> 5;
    int lane = threadIdx.x & 31;
    if (w >= N) return;
    float dd = g_dinv[w];
    const float2* h2v = reinterpret_cast<const float2*>(g_h2);
    float2 v = h2v[(long long)w * 32 + lane];
    float2 acc = make_float2(v.x * dd, v.y * dd);
    int j = g_rowptr[w];
    int j1 = g_pos[w];
    for (; j < j1; ++j) {
        int s0 = g_csr[j];
        float w0 = g_dinv[s0];
        float2 u0 = h2v[(long long)s0 * 32 + lane];
        acc.x = fmaf(u0.x, w0, acc.x); acc.y = fmaf(u0.y, w0, acc.y);
    }
    float2 bb = reinterpret_cast<const float2*>(b2)[lane];
    float2 o;
    o.x = fmaf(acc.x, dd, bb.x);
    o.y = fmaf(acc.y, dd, bb.y);
    reinterpret_cast<float2*>(out)[(long long)w * 32 + lane] = o;
}

// ======================= host-side stream/event (once) ======================
struct GcnStreams {
    cudaStream_t s1 = nullptr;
    cudaEvent_t e0 = nullptr, e1 = nullptr;
    bool ok = false;
    GcnStreams() {
        if (cudaStreamCreateWithFlags(&s1, cudaStreamNonBlocking) != cudaSuccess) return;
        if (cudaEventCreateWithFlags(&e0, cudaEventDisableTiming) != cudaSuccess) return;
        if (cudaEventCreateWithFlags(&e1, cudaEventDisableTiming) != cudaSuccess) return;
        ok = true;
    }
};
static GcnStreams g_str;

// ======================= launch ==============================================
extern "C" void kernel_launch(void* const* d_in, const int* in_sizes, int n_in,
                              void* d_out, int out_size) {
    const float* x   = (const float*)d_in[0];
    const void*  ei  = d_in[1];
    const float* W1  = (const float*)d_in[2];
    const float* b1  = (const float*)d_in[3];
    const float* W2  = (const float*)d_in[4];
    const float* b2  = (const float*)d_in[5];
    float*       out = (float*)d_out;

    const int N = in_sizes[0] / 128;
    const int E = in_sizes[1] / 2;
    const bool tc_ok = (in_sizes[2] == 128 * 128) && (in_sizes[4] == 128 * 64);

    const int TB = 256;
    const int nb = (N + SCAN_B - 1) / SCAN_B;
    const int ebl2 = (E / 2 + TB) / TB;

    const int smem1 = (2 * 64 * 136 + 2 * 128 * 136) * 2;   // 104448
    const int smem2 = (2 * 128 * 136 + 2 * 64 * 136) * 2;   // 104448
    cudaFuncSetAttribute(gemm1_mma,
                         cudaFuncAttributeMaxDynamicSharedMemorySize, smem1);
    cudaFuncSetAttribute(gemm2_mma,
                         cudaFuncAttributeMaxDynamicSharedMemorySize, smem2);

    const bool fork = g_str.ok;
    cudaStream_t sc = fork ? g_str.s1 : (cudaStream_t)0;

    if (fork) {
        cudaEventRecord(g_str.e0, 0);
        cudaStreamWaitEvent(sc, g_str.e0, 0);
    }

    // CSR build chain (side stream): deg -> scanA -> build
    deg_kernel<<<ebl2, TB, 0, sc>>>(ei, E, N);
    scanA_kernel<<<nb, SCAN_B, 0, sc>>>(N);
    build_kernel<<<ebl2, TB, 0, sc>>>(ei, E, N);

    // Main stream: prep (convert once) -> gemm1
    if (tc_ok) {
        prep_kernel<<<(N * 32 + TB - 1) / TB, TB>>>(x, W1, W2, N);
        gemm1_mma<<<(N + 63) / 64, 256, smem1>>>(N);
    } else {
        gemm1_simt<<<(N + 31) / 32, 256>>>(x, W1, N);
    }

    if (fork) {
        cudaEventRecord(g_str.e1, sc);
        cudaStreamWaitEvent((cudaStream_t)0, g_str.e1, 0);
    }

    if (tc_ok) {
        gather1_kernel<<<(N * 32 + TB - 1) / TB, TB>>>(b1, N);
        gemm2_mma<<<(N + 127) / 128, 256, smem2>>>(N);
        gather2_kernel<<<(N * 32 + TB - 1) / TB, TB>>>(b2, out, N);
    } else {
        gather1_fb<<<(N * 32 + TB - 1) / TB, TB>>>(b1, N);
        gemm2_simt<<<(N + 31) / 32, 128>>>(W2, N);
        gather2_fb<<<(N * 32 + TB - 1) / TB, TB>>>(b2, out, N);
    }
}